// round 11
// baseline (speedup 1.0000x reference)
#include <cuda_runtime.h>
#include <math.h>

#define BB 8
#define NN 256
#define DD 128
#define ROWS (BB*NN)          // 2048
#define EROWS (BB*NN*NN)      // 524288
#define BN_EPS 1e-5f
#define RPW 8                 // e-rows per warp
#define TI  4                 // i-rows per tail block

#define CHUNKS_TOTAL 8192     // 64 e-rows each
#define NSPLIT 4              // copy sub-kernels (2 batches each)
#define CHUNKS_PER_SPLIT (CHUNKS_TOTAL / NSPLIT)   // 2048
#define TAIL_BLKS 128         // per tail kernel: 128 blocks * 4 rows = 2 batches

// __device__ globals (zero at load; g_sum/g_sumsq re-zeroed by copy-A block 0
// each launch, stream-ordered before every tail kernel -> graph-replay safe)
__device__ float g_w[EROWS];
__device__ float g_Wt[DD*DD];
__device__ float g_h1[ROWS*DD];
__device__ float g_sum[DD];
__device__ float g_sumsq[DD];

// ---------------------------------------------------------------------------
// Copy sub-kernel: identical 6.4 TB/s hot path, parameterized by base chunk.
// do_init!=0 (first sub-kernel only): block 0 zeroes stats + transposes W.
// ---------------------------------------------------------------------------
__global__ void __launch_bounds__(256) k_copy(
    const float4* __restrict__ e,
    float4* __restrict__ out_e,
    const float* __restrict__ Wm,
    int base_chunk, int do_init)
{
    if (do_init && blockIdx.x == 0) {
        if (threadIdx.x < DD) {
            g_sum[threadIdx.x]   = 0.0f;
            g_sumsq[threadIdx.x] = 0.0f;
        }
        for (int i = threadIdx.x; i < DD*DD; i += 256) {
            int r = i >> 7, c = i & 127;
            g_Wt[c * DD + r] = Wm[i];
        }
    }
    size_t gw   = (size_t)(base_chunk + blockIdx.x) * 8 + (threadIdx.x >> 5);
    int    lane = threadIdx.x & 31;
    size_t r0   = gw * RPW;
    size_t base = r0 * 32 + lane;

    float4 v[RPW];
    #pragma unroll
    for (int k = 0; k < RPW; k++)
        v[k] = __ldcs(e + base + (size_t)k * 32);
    #pragma unroll
    for (int k = 0; k < RPW; k++)
        __stcs(out_e + base + (size_t)k * 32, v[k]);

    float s[RPW];
    #pragma unroll
    for (int k = 0; k < RPW; k++)
        s[k] = v[k].x*v[k].x + v[k].y*v[k].y + v[k].z*v[k].z + v[k].w*v[k].w;
    #pragma unroll
    for (int o = 16; o > 0; o >>= 1) {
        #pragma unroll
        for (int k = 0; k < RPW; k++)
            s[k] += __shfl_xor_sync(0xffffffffu, s[k], o);
    }
    if (lane == 0) {
        #pragma unroll
        for (int k = 0; k < RPW; k++)
            g_w[r0 + k] = sqrtf(s[k]);
    }
}

// ---------------------------------------------------------------------------
// Tail sub-kernel (R8 structure, no barrier / no BN apply): 128 blocks x 256,
// block handles TI=4 rows. softmax -> agg (j-split halves) -> linear via
// g_Wt -> relu -> y to g_h1 + one atomic stat pair per feature per block.
// Gated by a GRAPH EDGE on its copy sub-kernel (no device-side waiting).
// ---------------------------------------------------------------------------
__global__ void __launch_bounds__(256) k_tail(
    const float* __restrict__ h,
    const float* __restrict__ bias,
    int base_bi)
{
    int bi0 = base_bi + blockIdx.x * TI;
    int b   = bi0 >> 8;
    int i0  = bi0 & 255;
    int tid = threadIdx.x;
    int t    = tid & 127;
    int half = tid >> 7;
    int warp = tid >> 5, lane = tid & 31;

    __shared__ float sw[TI][NN];
    __shared__ float sacc[2][TI][DD];
    __shared__ float sx[TI][DD];
    __shared__ float pp[DD], pps[DD];

    // softmax: warps 0-3, one row each
    if (warp < TI) {
        const float* wrow = g_w + (size_t)(bi0 + warp) * NN;
        float v[NN/32];
        float m = -1e30f;
        #pragma unroll
        for (int k = 0; k < NN/32; k++) {
            v[k] = wrow[lane + 32*k];
            m = fmaxf(m, v[k]);
        }
        #pragma unroll
        for (int o = 16; o > 0; o >>= 1)
            m = fmaxf(m, __shfl_xor_sync(0xffffffffu, m, o));
        float sum = 0.0f;
        #pragma unroll
        for (int k = 0; k < NN/32; k++) {
            v[k] = __expf(v[k] - m);
            sum += v[k];
        }
        #pragma unroll
        for (int o = 16; o > 0; o >>= 1)
            sum += __shfl_xor_sync(0xffffffffu, sum, o);
        float inv = 1.0f / sum;
        #pragma unroll
        for (int k = 0; k < NN/32; k++)
            sw[warp][lane + 32*k] = v[k] * inv;
    }
    __syncthreads();

    // aggregation: half owns j in [half*128, +128) for all 4 rows
    const float* hb = h + (size_t)b * NN * DD;
    {
        float acc[TI] = {0.f, 0.f, 0.f, 0.f};
        int jbase = half * 128;
        for (int j0 = 0; j0 < 128; j0 += 16) {
            float hv[16];
            #pragma unroll
            for (int k = 0; k < 16; k++)
                hv[k] = hb[(jbase + j0 + k) * DD + t];
            #pragma unroll
            for (int r = 0; r < TI; r++) {
                const float4* swr = (const float4*)&sw[r][jbase + j0];
                #pragma unroll
                for (int q = 0; q < 4; q++) {
                    float4 p = swr[q];
                    acc[r] = fmaf(p.x, hv[q*4+0], acc[r]);
                    acc[r] = fmaf(p.y, hv[q*4+1], acc[r]);
                    acc[r] = fmaf(p.z, hv[q*4+2], acc[r]);
                    acc[r] = fmaf(p.w, hv[q*4+3], acc[r]);
                }
            }
        }
        #pragma unroll
        for (int r = 0; r < TI; r++)
            sacc[half][r][t] = acc[r];
    }
    __syncthreads();

    // combine halves; half owns rows {2h, 2h+1}
    #pragma unroll
    for (int rr = 0; rr < 2; rr++) {
        int r = half * 2 + rr;
        sx[r][t] = hb[(i0 + r) * DD + t] + sacc[0][r][t] + sacc[1][r][t];
    }
    __syncthreads();

    // linear via transposed W (coalesced) + relu
    float y[2];
    float bt = bias[t];
    y[0] = bt; y[1] = bt;
    for (int d0 = 0; d0 < DD; d0 += 16) {
        float wt[16];
        #pragma unroll
        for (int k = 0; k < 16; k++)
            wt[k] = g_Wt[(d0 + k) * DD + t];
        #pragma unroll
        for (int rr = 0; rr < 2; rr++) {
            const float4* xr = (const float4*)&sx[half*2 + rr][d0];
            #pragma unroll
            for (int q = 0; q < 4; q++) {
                float4 xv = xr[q];
                y[rr] = fmaf(xv.x, wt[q*4+0], y[rr]);
                y[rr] = fmaf(xv.y, wt[q*4+1], y[rr]);
                y[rr] = fmaf(xv.z, wt[q*4+2], y[rr]);
                y[rr] = fmaf(xv.w, wt[q*4+3], y[rr]);
            }
        }
    }

    float ls = 0.0f, lss = 0.0f;
    #pragma unroll
    for (int rr = 0; rr < 2; rr++) {
        y[rr] = fmaxf(y[rr], 0.0f);
        g_h1[(bi0 + half*2 + rr) * DD + t] = y[rr];
        ls  += y[rr];
        lss  = fmaf(y[rr], y[rr], lss);
    }
    if (half == 1) { pp[t] = ls; pps[t] = lss; }
    __syncthreads();
    if (half == 0) {
        atomicAdd(&g_sum[t],   ls  + pp[t]);
        atomicAdd(&g_sumsq[t], lss + pps[t]);
    }
}

// ---------------------------------------------------------------------------
// BN apply + residual (gated by graph edge on the last tail kernel).
// ---------------------------------------------------------------------------
__global__ void __launch_bounds__(128) k_bnapply(
    const float4* __restrict__ h,
    const float4* __restrict__ gamma,
    const float4* __restrict__ beta,
    float4* __restrict__ out_h)
{
    int lane = threadIdx.x & 31;         // float4 index within row
    int row  = blockIdx.x * 4 + (threadIdx.x >> 5);

    float4 s  = ((const float4*)g_sum)[lane];
    float4 ss = ((const float4*)g_sumsq)[lane];
    float4 gm = gamma[lane];
    float4 bb = beta[lane];

    const float inv = 1.0f / ROWS;
    float mx = s.x*inv, my = s.y*inv, mz = s.z*inv, mw = s.w*inv;
    float gx = gm.x * rsqrtf(ss.x*inv - mx*mx + BN_EPS);
    float gy = gm.y * rsqrtf(ss.y*inv - my*my + BN_EPS);
    float gz = gm.z * rsqrtf(ss.z*inv - mz*mz + BN_EPS);
    float gw = gm.w * rsqrtf(ss.w*inv - mw*mw + BN_EPS);
    float bx = bb.x - mx*gx, by = bb.y - my*gy, bz = bb.z - mz*gz, bw = bb.w - mw*gw;

    int idx = row * (DD/4) + lane;
    float4 v  = ((const float4*)g_h1)[idx];
    float4 hv = h[idx];
    float4 o;
    o.x = fmaf(v.x, gx, bx) + hv.x;
    o.y = fmaf(v.y, gy, by) + hv.y;
    o.z = fmaf(v.z, gz, bz) + hv.z;
    o.w = fmaf(v.w, gw, bw) + hv.w;
    out_h[idx] = o;
}

// ---------------------------------------------------------------------------
extern "C" void kernel_launch(void* const* d_in, const int* in_sizes, int n_in,
                              void* d_out, int out_size) {
    const float* h     = (const float*)d_in[0];   // (8,256,128)
    const float* e     = (const float*)d_in[1];   // (8,256,256,128)
    const float* Wm    = (const float*)d_in[2];   // (128,128)
    const float* bias  = (const float*)d_in[3];   // (128)
    const float* gamma = (const float*)d_in[4];   // (128)
    const float* beta  = (const float*)d_in[5];   // (128)

    float* out_h = (float*)d_out;                 // (8,256,128) first
    float* out_e = out_h + (size_t)ROWS * DD;     // then (8,256,256,128)

    // side stream + events created once, on the first (non-captured)
    // correctness call; capture-time uses them to build graph edges only.
    static cudaStream_t s1 = 0;
    static cudaEvent_t evc[NSPLIT], evj;
    if (!s1) {
        cudaStreamCreateWithFlags(&s1, cudaStreamNonBlocking);
        for (int i = 0; i < NSPLIT; i++)
            cudaEventCreateWithFlags(&evc[i], cudaEventDisableTiming);
        cudaEventCreateWithFlags(&evj, cudaEventDisableTiming);
    }

    // main stream: 4 copy sub-kernels (2 batches each), event after each
    for (int i = 0; i < NSPLIT; i++) {
        k_copy<<<CHUNKS_PER_SPLIT, 256>>>((const float4*)e, (float4*)out_e,
                                          Wm, i * CHUNKS_PER_SPLIT, i == 0);
        cudaEventRecord(evc[i], 0);
    }

    // side stream: tail_i gated on copy_i by graph edge (no device spinning)
    for (int i = 0; i < NSPLIT; i++) {
        cudaStreamWaitEvent(s1, evc[i], 0);
        k_tail<<<TAIL_BLKS, 256, 0, s1>>>(h, bias, i * (ROWS / NSPLIT));
    }
    cudaEventRecord(evj, s1);

    // join: BN apply after all tails
    cudaStreamWaitEvent(0, evj, 0);
    k_bnapply<<<ROWS / 4, 128>>>((const float4*)h, (const float4*)gamma,
                                 (const float4*)beta, (float4*)out_h);
}

// round 12
// speedup vs baseline: 1.1796x; 1.1796x over previous
#include <cuda_runtime.h>
#include <math.h>

#define BB 8
#define NN 256
#define DD 128
#define ROWS (BB*NN)          // 2048
#define EROWS (BB*NN*NN)      // 524288
#define BN_EPS 1e-5f
#define RPW 8                 // e-rows per warp in copy kernel
#define TI  4                 // i-rows per tail block
#define NB_TAIL (ROWS/TI)     // 512 tail blocks
#define NB_COPY  8192

// __device__ globals (zero at load; stats re-zeroed by copy block 0 every
// launch, stream-ordered before the tail -> graph-replay safe)
__device__ float  g_w[EROWS];
__device__ float4 g_Wtp[(DD/4)*DD];    // packed W: [d4][t] = W[t][4d4..+3]
__device__ float4 g_hp[BB*(NN/4)*DD];  // packed h: [b][j4][t] = h[b][4j4..+3][t]
__device__ float  g_h1[ROWS*DD];
__device__ float  g_sum[DD];
__device__ float  g_sumsq[DD];

// ---------------------------------------------------------------------------
// Kernel 1: norm + copy of e (6.8 TB/s effective hot path untouched).
// Blocks 0..8 additionally prepare the tail's packed operands (hidden work):
//   block 0: zero stats + pack W into g_Wtp
//   block 1+k (k=0..7): pack h[batch k] into g_hp
// ---------------------------------------------------------------------------
__global__ void __launch_bounds__(256) k_norm_copy(
    const float4* __restrict__ e,
    float4* __restrict__ out_e,
    const float* __restrict__ Wm,
    const float* __restrict__ h)
{
    if (blockIdx.x == 0) {
        if (threadIdx.x < DD) {
            g_sum[threadIdx.x]   = 0.0f;
            g_sumsq[threadIdx.x] = 0.0f;
        }
        // pack W: thread reads W[t][4d4..+3] (contiguous float4), writes [d4][t]
        for (int i = threadIdx.x; i < DD * (DD/4); i += 256) {
            int t  = i / (DD/4);
            int d4 = i % (DD/4);
            g_Wtp[d4 * DD + t] = ((const float4*)Wm)[t * (DD/4) + d4];
        }
    } else if (blockIdx.x <= BB) {
        // pack h[batch b]: micro-tiles of 4 rows x 4 feats
        int b = blockIdx.x - 1;
        const float4* hb4 = (const float4*)(h + (size_t)b * NN * DD);
        float4* out = g_hp + (size_t)b * (NN/4) * DD;
        // 64 j4-groups x 32 t4-groups = 2048 tiles, 8 per thread
        for (int tile = threadIdx.x; tile < (NN/4)*(DD/4); tile += 256) {
            int j4 = tile >> 5;            // 0..63
            int t4 = tile & 31;            // 0..31
            float4 r0 = hb4[(j4*4 + 0) * (DD/4) + t4];
            float4 r1 = hb4[(j4*4 + 1) * (DD/4) + t4];
            float4 r2 = hb4[(j4*4 + 2) * (DD/4) + t4];
            float4 r3 = hb4[(j4*4 + 3) * (DD/4) + t4];
            out[j4 * DD + t4*4 + 0] = make_float4(r0.x, r1.x, r2.x, r3.x);
            out[j4 * DD + t4*4 + 1] = make_float4(r0.y, r1.y, r2.y, r3.y);
            out[j4 * DD + t4*4 + 2] = make_float4(r0.z, r1.z, r2.z, r3.z);
            out[j4 * DD + t4*4 + 3] = make_float4(r0.w, r1.w, r2.w, r3.w);
        }
    }
    size_t gw   = (size_t)((blockIdx.x * blockDim.x + threadIdx.x) >> 5);
    int    lane = threadIdx.x & 31;
    size_t r0i  = gw * RPW;
    size_t base = r0i * 32 + lane;

    float4 v[RPW];
    #pragma unroll
    for (int k = 0; k < RPW; k++)
        v[k] = __ldcs(e + base + (size_t)k * 32);
    #pragma unroll
    for (int k = 0; k < RPW; k++)
        __stcs(out_e + base + (size_t)k * 32, v[k]);

    float s[RPW];
    #pragma unroll
    for (int k = 0; k < RPW; k++)
        s[k] = v[k].x*v[k].x + v[k].y*v[k].y + v[k].z*v[k].z + v[k].w*v[k].w;
    #pragma unroll
    for (int o = 16; o > 0; o >>= 1) {
        #pragma unroll
        for (int k = 0; k < RPW; k++)
            s[k] += __shfl_xor_sync(0xffffffffu, s[k], o);
    }
    if (lane == 0) {
        #pragma unroll
        for (int k = 0; k < RPW; k++)
            g_w[r0i + k] = sqrtf(s[k]);
    }
}

// ---------------------------------------------------------------------------
// Kernel 2: tail. 512 blocks x 512 threads, TI=4 rows per block.
//   t = tid&127 (feature), q = tid>>7 (quarter: j-split in agg, row q after).
//   All hot loads are packed float4 (4x fewer LDG issues than R9).
// ---------------------------------------------------------------------------
__global__ void __launch_bounds__(512) k_tail(
    const float* __restrict__ h,
    const float* __restrict__ bias)
{
    int bi0 = blockIdx.x * TI;
    int b   = bi0 >> 8;
    int i0  = bi0 & 255;
    int tid = threadIdx.x;
    int t    = tid & 127;
    int q    = tid >> 7;
    int warp = tid >> 5, lane = tid & 31;

    __shared__ float sw[TI][NN];       // softmax probs (4 KB)
    __shared__ float sacc[4][TI][DD];  // quarter agg partials (8 KB)
    __shared__ float sx[TI][DD];       // pre-linear activations (2 KB)

    // --- softmax: warps 0-3, one row each ---
    if (warp < TI) {
        const float* wrow = g_w + (size_t)(bi0 + warp) * NN;
        float v[NN/32];
        float m = -1e30f;
        #pragma unroll
        for (int k = 0; k < NN/32; k++) {
            v[k] = wrow[lane + 32*k];
            m = fmaxf(m, v[k]);
        }
        #pragma unroll
        for (int o = 16; o > 0; o >>= 1)
            m = fmaxf(m, __shfl_xor_sync(0xffffffffu, m, o));
        float sum = 0.0f;
        #pragma unroll
        for (int k = 0; k < NN/32; k++) {
            v[k] = __expf(v[k] - m);
            sum += v[k];
        }
        #pragma unroll
        for (int o = 16; o > 0; o >>= 1)
            sum += __shfl_xor_sync(0xffffffffu, sum, o);
        float inv = 1.0f / sum;
        #pragma unroll
        for (int k = 0; k < NN/32; k++)
            sw[warp][lane + 32*k] = v[k] * inv;
    }
    __syncthreads();

    // --- agg: quarter q covers j4 in [16q, 16q+16); packed float4 loads ---
    {
        const float4* hp = g_hp + (size_t)b * (NN/4) * DD;
        float acc[TI] = {0.f, 0.f, 0.f, 0.f};
        int j4base = q * 16;
        #pragma unroll 4
        for (int jj = 0; jj < 16; jj++) {
            int j4 = j4base + jj;
            float4 hv = hp[j4 * DD + t];        // h[4j4..+3][t]
            #pragma unroll
            for (int r = 0; r < TI; r++) {
                float4 p = *(const float4*)&sw[r][j4 * 4];  // broadcast
                acc[r] += p.x*hv.x + p.y*hv.y + p.z*hv.z + p.w*hv.w;
            }
        }
        #pragma unroll
        for (int r = 0; r < TI; r++)
            sacc[q][r][t] = acc[r];
    }
    __syncthreads();

    // --- combine quarters; quarter q owns row q from here on ---
    const float* hb = h + (size_t)b * NN * DD;
    float hres = hb[(i0 + q) * DD + t];
    sx[q][t] = hres + sacc[0][q][t] + sacc[1][q][t]
                    + sacc[2][q][t] + sacc[3][q][t];
    __syncthreads();

    // --- linear via packed Wt: y = bias[t] + sum_d sx[q][d]*W[t][d] ---
    float y = bias[t];
    #pragma unroll 8
    for (int d4 = 0; d4 < DD/4; d4++) {
        float4 wt = g_Wtp[d4 * DD + t];          // coalesced, L1-hot
        float4 xv = *(const float4*)&sx[q][d4 * 4];  // broadcast
        y += xv.x*wt.x + xv.y*wt.y + xv.z*wt.z + xv.w*wt.w;
    }
    y = fmaxf(y, 0.0f);
    g_h1[(bi0 + q) * DD + t] = y;

    // --- BN stats: combine quarters in smem, 1 atomic pair per feature ---
    float* sy  = &sacc[0][0][0];
    float* syy = &sacc[2][0][0];
    sy [q * DD + t] = y;
    syy[q * DD + t] = y * y;
    __syncthreads();
    if (q == 0) {
        float ls  = sy [t] + sy [DD + t] + sy [2*DD + t] + sy [3*DD + t];
        float lss = syy[t] + syy[DD + t] + syy[2*DD + t] + syy[3*DD + t];
        atomicAdd(&g_sum[t],   ls);
        atomicAdd(&g_sumsq[t], lss);
    }
}

// ---------------------------------------------------------------------------
// Kernel 3: BN apply + residual (float4; 512 blocks x 128 thr, 4 rows each)
// ---------------------------------------------------------------------------
__global__ void __launch_bounds__(128) k_bnapply(
    const float4* __restrict__ h,
    const float4* __restrict__ gamma,
    const float4* __restrict__ beta,
    float4* __restrict__ out_h)
{
    int lane = threadIdx.x & 31;
    int row  = blockIdx.x * 4 + (threadIdx.x >> 5);

    float4 s  = ((const float4*)g_sum)[lane];
    float4 ss = ((const float4*)g_sumsq)[lane];
    float4 gm = gamma[lane];
    float4 bb = beta[lane];

    const float inv = 1.0f / ROWS;
    float mx = s.x*inv, my = s.y*inv, mz = s.z*inv, mw = s.w*inv;
    float gx = gm.x * rsqrtf(ss.x*inv - mx*mx + BN_EPS);
    float gy = gm.y * rsqrtf(ss.y*inv - my*my + BN_EPS);
    float gz = gm.z * rsqrtf(ss.z*inv - mz*mz + BN_EPS);
    float gw = gm.w * rsqrtf(ss.w*inv - mw*mw + BN_EPS);
    float bx = bb.x - mx*gx, by = bb.y - my*gy;
    float bz = bb.z - mz*gz, bw = bb.w - mw*gw;

    int idx = row * (DD/4) + lane;
    float4 v  = ((const float4*)g_h1)[idx];
    float4 hv = h[idx];
    float4 o;
    o.x = fmaf(v.x, gx, bx) + hv.x;
    o.y = fmaf(v.y, gy, by) + hv.y;
    o.z = fmaf(v.z, gz, bz) + hv.z;
    o.w = fmaf(v.w, gw, bw) + hv.w;
    out_h[idx] = o;
}

// ---------------------------------------------------------------------------
extern "C" void kernel_launch(void* const* d_in, const int* in_sizes, int n_in,
                              void* d_out, int out_size) {
    const float* h     = (const float*)d_in[0];   // (8,256,128)
    const float* e     = (const float*)d_in[1];   // (8,256,256,128)
    const float* Wm    = (const float*)d_in[2];   // (128,128)
    const float* bias  = (const float*)d_in[3];   // (128)
    const float* gamma = (const float*)d_in[4];   // (128)
    const float* beta  = (const float*)d_in[5];   // (128)

    float* out_h = (float*)d_out;                 // (8,256,128) first
    float* out_e = out_h + (size_t)ROWS * DD;     // then (8,256,256,128)

    k_norm_copy<<<NB_COPY, 256>>>((const float4*)e, (float4*)out_e, Wm, h);
    k_tail<<<NB_TAIL, 512>>>(h, bias);
    k_bnapply<<<ROWS / 4, 128>>>((const float4*)h, (const float4*)gamma,
                                 (const float4*)beta, (float4*)out_h);
}

// round 13
// speedup vs baseline: 1.2585x; 1.0669x over previous
#include <cuda_runtime.h>
#include <math.h>

#define BB 8
#define NN 256
#define DD 128
#define ROWS (BB*NN)          // 2048
#define EROWS (BB*NN*NN)      // 524288
#define BN_EPS 1e-5f
#define RPW 8                 // e-rows per warp in copy kernel
#define TI  4                 // i-rows per tail block
#define NB_TAIL (ROWS/TI)     // 512 tail blocks
#define NB_COPY  8192

// __device__ globals (zero at load; stats/barrier re-zeroed by copy block 0
// every launch, stream-ordered before the tail -> graph-replay safe)
__device__ float  g_w[EROWS];
__device__ float4 g_Wtp[(DD/4)*DD];    // packed W: [d4][t] = W[t][4d4..+3]
__device__ float4 g_hp[BB*(NN/4)*DD];  // packed h: [b][j4][t] = h[b][4j4..+3][t]
__device__ float  g_sum[DD];
__device__ float  g_sumsq[DD];
__device__ int    g_bar;

// ---------------------------------------------------------------------------
// Kernel 1: norm + copy of e (6.4 TB/s hot path untouched).
// Block 0: zero stats/barrier + pack W.  Blocks 1..8: pack h per batch.
// ---------------------------------------------------------------------------
__global__ void __launch_bounds__(256) k_norm_copy(
    const float4* __restrict__ e,
    float4* __restrict__ out_e,
    const float* __restrict__ Wm,
    const float* __restrict__ h)
{
    if (blockIdx.x == 0) {
        if (threadIdx.x < DD) {
            g_sum[threadIdx.x]   = 0.0f;
            g_sumsq[threadIdx.x] = 0.0f;
            if (threadIdx.x == 0) g_bar = 0;
        }
        for (int i = threadIdx.x; i < DD * (DD/4); i += 256) {
            int t  = i / (DD/4);
            int d4 = i % (DD/4);
            g_Wtp[d4 * DD + t] = ((const float4*)Wm)[t * (DD/4) + d4];
        }
    } else if (blockIdx.x <= BB) {
        int b = blockIdx.x - 1;
        const float4* hb4 = (const float4*)(h + (size_t)b * NN * DD);
        float4* out = g_hp + (size_t)b * (NN/4) * DD;
        for (int tile = threadIdx.x; tile < (NN/4)*(DD/4); tile += 256) {
            int j4 = tile >> 5;
            int t4 = tile & 31;
            float4 r0 = hb4[(j4*4 + 0) * (DD/4) + t4];
            float4 r1 = hb4[(j4*4 + 1) * (DD/4) + t4];
            float4 r2 = hb4[(j4*4 + 2) * (DD/4) + t4];
            float4 r3 = hb4[(j4*4 + 3) * (DD/4) + t4];
            out[j4 * DD + t4*4 + 0] = make_float4(r0.x, r1.x, r2.x, r3.x);
            out[j4 * DD + t4*4 + 1] = make_float4(r0.y, r1.y, r2.y, r3.y);
            out[j4 * DD + t4*4 + 2] = make_float4(r0.z, r1.z, r2.z, r3.z);
            out[j4 * DD + t4*4 + 3] = make_float4(r0.w, r1.w, r2.w, r3.w);
        }
    }
    size_t gw   = (size_t)((blockIdx.x * blockDim.x + threadIdx.x) >> 5);
    int    lane = threadIdx.x & 31;
    size_t r0i  = gw * RPW;
    size_t base = r0i * 32 + lane;

    float4 v[RPW];
    #pragma unroll
    for (int k = 0; k < RPW; k++)
        v[k] = __ldcs(e + base + (size_t)k * 32);
    #pragma unroll
    for (int k = 0; k < RPW; k++)
        __stcs(out_e + base + (size_t)k * 32, v[k]);

    float s[RPW];
    #pragma unroll
    for (int k = 0; k < RPW; k++)
        s[k] = v[k].x*v[k].x + v[k].y*v[k].y + v[k].z*v[k].z + v[k].w*v[k].w;
    #pragma unroll
    for (int o = 16; o > 0; o >>= 1) {
        #pragma unroll
        for (int k = 0; k < RPW; k++)
            s[k] += __shfl_xor_sync(0xffffffffu, s[k], o);
    }
    if (lane == 0) {
        #pragma unroll
        for (int k = 0; k < RPW; k++)
            g_w[r0i + k] = sqrtf(s[k]);
    }
}

// ---------------------------------------------------------------------------
// Kernel 2: entire tail. 512 blocks x 256 threads, launch_bounds(256,4)
// => regs<=64, 4 blocks/SM guaranteed => 592 slots >= 512 (barrier safe).
//   t = tid&127 (feature), half = tid>>7.
//   A: softmax (warps 0-3, float4 loads)
//   B: agg — half owns 32 j4's for ALL 4 rows (hv reused 4x), MLP=8
//   C: sx build; half owns rows {2h,2h+1} residuals
//   D: linear — half owns 64 d's for ALL 4 rows (Wt reused 4x), partials
//   E: combine, relu, BN stats -> grid barrier -> BN apply from registers
// ---------------------------------------------------------------------------
__global__ void __launch_bounds__(256, 4) k_tail(
    const float* __restrict__ h,
    const float* __restrict__ bias,
    const float* __restrict__ gamma,
    const float* __restrict__ beta,
    float* __restrict__ out_h)
{
    int bi0 = blockIdx.x * TI;
    int b   = bi0 >> 8;
    int i0  = bi0 & 255;
    int tid = threadIdx.x;
    int t    = tid & 127;
    int half = tid >> 7;
    int warp = tid >> 5, lane = tid & 31;

    __shared__ float sw[TI][NN];          // softmax probs   (4 KB)
    __shared__ float spart[2][TI][DD];    // agg partials    (4 KB)
    __shared__ float sx[TI][DD];          // pre-linear acts (2 KB)
    __shared__ float splin[2][TI][DD];    // linear partials (4 KB)
    __shared__ float pp[DD], pps[DD];     // BN partials     (1 KB)

    // --- A: softmax, warps 0-3 own one row each; float4 loads ---
    if (warp < TI) {
        const float4* wrow4 = (const float4*)(g_w + (size_t)(bi0 + warp) * NN);
        float4 a = wrow4[lane * 2];
        float4 c = wrow4[lane * 2 + 1];
        float m = fmaxf(fmaxf(fmaxf(a.x, a.y), fmaxf(a.z, a.w)),
                        fmaxf(fmaxf(c.x, c.y), fmaxf(c.z, c.w)));
        #pragma unroll
        for (int o = 16; o > 0; o >>= 1)
            m = fmaxf(m, __shfl_xor_sync(0xffffffffu, m, o));
        a.x = __expf(a.x - m); a.y = __expf(a.y - m);
        a.z = __expf(a.z - m); a.w = __expf(a.w - m);
        c.x = __expf(c.x - m); c.y = __expf(c.y - m);
        c.z = __expf(c.z - m); c.w = __expf(c.w - m);
        float sum = a.x + a.y + a.z + a.w + c.x + c.y + c.z + c.w;
        #pragma unroll
        for (int o = 16; o > 0; o >>= 1)
            sum += __shfl_xor_sync(0xffffffffu, sum, o);
        float inv = 1.0f / sum;
        a.x *= inv; a.y *= inv; a.z *= inv; a.w *= inv;
        c.x *= inv; c.y *= inv; c.z *= inv; c.w *= inv;
        float4* swr4 = (float4*)&sw[warp][0];
        swr4[lane * 2]     = a;
        swr4[lane * 2 + 1] = c;
    }
    __syncthreads();

    // --- B: agg. half owns j4 in [32h, 32h+32); 8-deep load batches ---
    {
        const float4* hp = g_hp + (size_t)b * (NN/4) * DD;
        float acc[TI] = {0.f, 0.f, 0.f, 0.f};
        int j4b = half * 32;
        #pragma unroll
        for (int cch = 0; cch < 4; cch++) {
            float4 hv[8];
            #pragma unroll
            for (int k = 0; k < 8; k++)
                hv[k] = hp[(j4b + cch*8 + k) * DD + t];
            #pragma unroll
            for (int k = 0; k < 8; k++) {
                int j4 = j4b + cch*8 + k;
                #pragma unroll
                for (int r = 0; r < TI; r++) {
                    float4 p = *(const float4*)&sw[r][j4 * 4];  // broadcast
                    acc[r] = fmaf(p.x, hv[k].x, acc[r]);
                    acc[r] = fmaf(p.y, hv[k].y, acc[r]);
                    acc[r] = fmaf(p.z, hv[k].z, acc[r]);
                    acc[r] = fmaf(p.w, hv[k].w, acc[r]);
                }
            }
        }
        #pragma unroll
        for (int r = 0; r < TI; r++)
            spart[half][r][t] = acc[r];
    }
    __syncthreads();

    // --- C: build sx; half owns rows {2h, 2h+1} residuals ---
    const float* hb = h + (size_t)b * NN * DD;
    float hres[2];
    #pragma unroll
    for (int rr = 0; rr < 2; rr++) {
        int r = half * 2 + rr;
        hres[rr] = hb[(i0 + r) * DD + t];
        sx[r][t] = hres[rr] + spart[0][r][t] + spart[1][r][t];
    }
    __syncthreads();

    // --- D: linear partials. half owns d4 in [16h, 16h+16) for all rows ---
    {
        float lp[TI] = {0.f, 0.f, 0.f, 0.f};
        int d4b = half * 16;
        #pragma unroll
        for (int cch = 0; cch < 4; cch++) {
            float4 wt[4];
            #pragma unroll
            for (int k = 0; k < 4; k++)
                wt[k] = g_Wtp[(d4b + cch*4 + k) * DD + t];
            #pragma unroll
            for (int k = 0; k < 4; k++) {
                int d4 = d4b + cch*4 + k;
                #pragma unroll
                for (int r = 0; r < TI; r++) {
                    float4 xv = *(const float4*)&sx[r][d4 * 4];  // broadcast
                    lp[r] = fmaf(xv.x, wt[k].x, lp[r]);
                    lp[r] = fmaf(xv.y, wt[k].y, lp[r]);
                    lp[r] = fmaf(xv.z, wt[k].z, lp[r]);
                    lp[r] = fmaf(xv.w, wt[k].w, lp[r]);
                }
            }
        }
        #pragma unroll
        for (int r = 0; r < TI; r++)
            splin[half][r][t] = lp[r];
    }
    __syncthreads();

    // --- E: combine, relu, BN stats; half owns rows {2h, 2h+1} ---
    float y[2];
    float bt = bias[t];
    float ls = 0.0f, lss = 0.0f;
    #pragma unroll
    for (int rr = 0; rr < 2; rr++) {
        int r = half * 2 + rr;
        y[rr] = fmaxf(bt + splin[0][r][t] + splin[1][r][t], 0.0f);
        ls  += y[rr];
        lss  = fmaf(y[rr], y[rr], lss);
    }
    if (half == 1) { pp[t] = ls; pps[t] = lss; }
    __syncthreads();
    if (half == 0) {
        atomicAdd(&g_sum[t],   ls  + pp[t]);
        atomicAdd(&g_sumsq[t], lss + pps[t]);
    }

    // --- grid barrier (512 blocks co-resident by launch_bounds(256,4)) ---
    __syncthreads();
    if (tid == 0) {
        __threadfence();
        atomicAdd(&g_bar, 1);
        while (atomicAdd(&g_bar, 0) < NB_TAIL) __nanosleep(64);
    }
    __syncthreads();
    __threadfence();

    // --- BN apply + residual straight from registers ---
    float s  = __ldcg(&g_sum[t]);
    float ss = __ldcg(&g_sumsq[t]);
    float mean = s * (1.0f / ROWS);
    float var  = ss * (1.0f / ROWS) - mean * mean;
    float g  = gamma[t] * rsqrtf(var + BN_EPS);
    float b2 = beta[t] - mean * g;
    #pragma unroll
    for (int rr = 0; rr < 2; rr++) {
        int r = half * 2 + rr;
        out_h[(bi0 + r) * DD + t] = fmaf(y[rr], g, b2) + hres[rr];
    }
}

// ---------------------------------------------------------------------------
extern "C" void kernel_launch(void* const* d_in, const int* in_sizes, int n_in,
                              void* d_out, int out_size) {
    const float* h     = (const float*)d_in[0];   // (8,256,128)
    const float* e     = (const float*)d_in[1];   // (8,256,256,128)
    const float* Wm    = (const float*)d_in[2];   // (128,128)
    const float* bias  = (const float*)d_in[3];   // (128)
    const float* gamma = (const float*)d_in[4];   // (128)
    const float* beta  = (const float*)d_in[5];   // (128)

    float* out_h = (float*)d_out;                 // (8,256,128) first
    float* out_e = out_h + (size_t)ROWS * DD;     // then (8,256,256,128)

    k_norm_copy<<<NB_COPY, 256>>>((const float4*)e, (float4*)out_e, Wm, h);
    k_tail<<<NB_TAIL, 256>>>(h, bias, gamma, beta, out_h);
}